// round 1
// baseline (speedup 1.0000x reference)
#include <cuda_runtime.h>

#define NB 32
#define NCH 3
#define THREADS 128
#define B_PER_CHUNK 12
#define CHUNK_ELEMS (512*512)        // elements per (n,c) chunk = 262144
#define CHUNK_F4   (CHUNK_ELEMS/4)   // 65536 float4 per chunk
#define NCHUNKS    (16*3)            // 48

// Global accumulators (fp64 for accuracy; tiny atomic count)
__device__ double g_sum_p[NCH * NB];
__device__ double g_sum_t[NCH * NB];
__device__ double g_cnt [NCH * NB];

__global__ void init_kernel() {
    int i = threadIdx.x;
    if (i < NCH * NB) {
        g_sum_p[i] = 0.0;
        g_sum_t[i] = 0.0;
        g_cnt [i] = 0.0;
    }
}

__global__ __launch_bounds__(THREADS, 4)
void hist_kernel(const float4* __restrict__ pred,
                 const float4* __restrict__ targ,
                 const float4* __restrict__ x)
{
    // Per-thread privatized histograms: hist[bin*THREADS + tid]
    // bank = tid % 32  -> conflict-free RMW, zero atomics in hot path.
    __shared__ float sp[NB * THREADS];
    __shared__ float st[NB * THREADS];
    __shared__ float sc[NB * THREADS];

    const int tid = threadIdx.x;

    #pragma unroll
    for (int b = 0; b < NB; b++) {
        sp[b * THREADS + tid] = 0.0f;
        st[b * THREADS + tid] = 0.0f;
        sc[b * THREADS + tid] = 0.0f;
    }
    __syncthreads();

    const int chunk = blockIdx.x / B_PER_CHUNK;   // (n*3 + c)
    const int sub   = blockIdx.x % B_PER_CHUNK;
    const int chan  = chunk % NCH;
    const size_t base = (size_t)chunk * CHUNK_F4;

    for (int i = sub * THREADS + tid; i < CHUNK_F4; i += B_PER_CHUNK * THREADS) {
        float4 xv = x   [base + i];
        float4 pv = pred[base + i];
        float4 tv = targ[base + i];

        // component 0..3
        {
            float xc = xv.x;
            if (xc >= 0.0f && xc < 1.0f) {
                int b = (int)(xc * 32.0f);
                int a = b * THREADS + tid;
                sp[a] += pv.x; st[a] += tv.x; sc[a] += 1.0f;
            }
        }
        {
            float xc = xv.y;
            if (xc >= 0.0f && xc < 1.0f) {
                int b = (int)(xc * 32.0f);
                int a = b * THREADS + tid;
                sp[a] += pv.y; st[a] += tv.y; sc[a] += 1.0f;
            }
        }
        {
            float xc = xv.z;
            if (xc >= 0.0f && xc < 1.0f) {
                int b = (int)(xc * 32.0f);
                int a = b * THREADS + tid;
                sp[a] += pv.z; st[a] += tv.z; sc[a] += 1.0f;
            }
        }
        {
            float xc = xv.w;
            if (xc >= 0.0f && xc < 1.0f) {
                int b = (int)(xc * 32.0f);
                int a = b * THREADS + tid;
                sp[a] += pv.w; st[a] += tv.w; sc[a] += 1.0f;
            }
        }
    }
    __syncthreads();

    // Block reduce: 128 threads = 32 bins x 4 quarters.
    // Rotated k-index keeps banks distinct across lanes of a warp.
    const int bin = tid >> 2;
    const int j   = tid & 3;
    const int bi  = bin * THREADS + j * 32;

    float vp = 0.0f, vt = 0.0f, vc = 0.0f;
    #pragma unroll
    for (int k = 0; k < 32; k++) {
        int kk = (k + tid) & 31;
        vp += sp[bi + kk];
        vt += st[bi + kk];
        vc += sc[bi + kk];
    }

    // combine the 4 quarters (lanes tid%4 == 0..3, contiguous in warp)
    vp += __shfl_down_sync(0xffffffffu, vp, 1);
    vt += __shfl_down_sync(0xffffffffu, vt, 1);
    vc += __shfl_down_sync(0xffffffffu, vc, 1);
    vp += __shfl_down_sync(0xffffffffu, vp, 2);
    vt += __shfl_down_sync(0xffffffffu, vt, 2);
    vc += __shfl_down_sync(0xffffffffu, vc, 2);

    if (j == 0) {
        int g = chan * NB + bin;
        atomicAdd(&g_sum_p[g], (double)vp);
        atomicAdd(&g_sum_t[g], (double)vt);
        atomicAdd(&g_cnt [g], (double)vc);
    }
}

__global__ void final_kernel(float* __restrict__ out) {
    __shared__ float buf[128];
    int i = threadIdx.x;
    float d = 0.0f;
    if (i < NCH * NB) {
        double cnt = g_cnt[i];
        if (cnt > 0.0) {
            float mp = (float)(g_sum_p[i] / cnt);
            float mt = (float)(g_sum_t[i] / cnt);
            d = fabsf(mp - mt);
        }
    }
    buf[i] = d;
    __syncthreads();
    #pragma unroll
    for (int s = 64; s > 0; s >>= 1) {
        if (i < s) buf[i] += buf[i + s];
        __syncthreads();
    }
    if (i == 0) out[0] = buf[0] / 96.0f;
}

extern "C" void kernel_launch(void* const* d_in, const int* in_sizes, int n_in,
                              void* d_out, int out_size)
{
    const float4* pred = (const float4*)d_in[0];
    const float4* targ = (const float4*)d_in[1];
    const float4* x    = (const float4*)d_in[2];
    float* out = (float*)d_out;

    init_kernel<<<1, 128>>>();
    hist_kernel<<<NCHUNKS * B_PER_CHUNK, THREADS>>>(pred, targ, x);
    final_kernel<<<1, 128>>>(out);
}

// round 2
// speedup vs baseline: 1.3365x; 1.3365x over previous
#include <cuda_runtime.h>

#define NB 32
#define NCH 3
#define THREADS 128
#define B_PER_CHUNK 16
#define CHUNK_ELEMS (512*512)        // elements per (n,c) chunk
#define CHUNK_F4   (CHUNK_ELEMS/4)   // 65536 float4 per chunk
#define NCHUNKS    (16*3)            // 48
#define STRIDE     (B_PER_CHUNK*THREADS)   // 2048

// Global accumulators. Zero-initialized at module load; final_kernel resets
// them after every read, so each kernel_launch call starts from zero.
__device__ double g_sum_d[NCH * NB];
__device__ double g_cnt [NCH * NB];

__device__ __forceinline__ void accum(float2* h, float xc, float pc, float tc, int tid)
{
    if (xc >= 0.0f && xc < 1.0f) {
        int b = (int)(xc * 32.0f);
        float2* e = &h[b * THREADS + tid];
        float2 v = *e;                 // LDS.64, conflict-free (2-phase)
        v.x += pc - tc;
        v.y += 1.0f;
        *e = v;                        // STS.64
    }
}

__global__ __launch_bounds__(THREADS, 6)
void hist_kernel(const float4* __restrict__ pred,
                 const float4* __restrict__ targ,
                 const float4* __restrict__ x)
{
    // Per-thread privatized {sum(p-t), count} histogram: h[bin*128 + tid].
    // 8B elements; lane stride 8B -> conflict-free LDS.64/STS.64 RMW, no atomics.
    __shared__ float2 h[NB * THREADS];

    const int tid = threadIdx.x;

    #pragma unroll
    for (int b = 0; b < NB; b++)
        h[b * THREADS + tid] = make_float2(0.0f, 0.0f);
    __syncthreads();

    const int chunk = blockIdx.x / B_PER_CHUNK;   // (n*3 + c)
    const int sub   = blockIdx.x % B_PER_CHUNK;
    const int chan  = chunk % NCH;
    const size_t base = (size_t)chunk * CHUNK_F4;

    // 32 slots per thread, processed as 16 pairs {i, i+STRIDE} for 6-deep MLP.
    int i = sub * THREADS + tid;
    #pragma unroll 2
    for (int k = 0; k < CHUNK_F4 / (2 * STRIDE); k++, i += 2 * STRIDE) {
        float4 xa = __ldcs(&x   [base + i]);
        float4 pa = __ldcs(&pred[base + i]);
        float4 ta = __ldcs(&targ[base + i]);
        float4 xb = __ldcs(&x   [base + i + STRIDE]);
        float4 pb = __ldcs(&pred[base + i + STRIDE]);
        float4 tb = __ldcs(&targ[base + i + STRIDE]);

        accum(h, xa.x, pa.x, ta.x, tid);
        accum(h, xa.y, pa.y, ta.y, tid);
        accum(h, xa.z, pa.z, ta.z, tid);
        accum(h, xa.w, pa.w, ta.w, tid);

        accum(h, xb.x, pb.x, tb.x, tid);
        accum(h, xb.y, pb.y, tb.y, tid);
        accum(h, xb.z, pb.z, tb.z, tid);
        accum(h, xb.w, pb.w, tb.w, tid);
    }
    __syncthreads();

    // Block reduce: 128 threads = 32 bins x 4 quarters of 32 entries.
    // Rotated k-index keeps the 8B accesses spread across banks.
    const int bin = tid >> 2;
    const int j   = tid & 3;
    const int bi  = bin * THREADS + j * 32;

    float vd = 0.0f, vc = 0.0f;
    #pragma unroll
    for (int k = 0; k < 32; k++) {
        int kk = (k + tid) & 31;
        float2 e = h[bi + kk];
        vd += e.x;
        vc += e.y;
    }

    vd += __shfl_down_sync(0xffffffffu, vd, 1);
    vc += __shfl_down_sync(0xffffffffu, vc, 1);
    vd += __shfl_down_sync(0xffffffffu, vd, 2);
    vc += __shfl_down_sync(0xffffffffu, vc, 2);

    if (j == 0) {
        int g = chan * NB + bin;
        atomicAdd(&g_sum_d[g], (double)vd);
        atomicAdd(&g_cnt [g], (double)vc);
    }
}

__global__ void final_kernel(float* __restrict__ out) {
    __shared__ float buf[128];
    int i = threadIdx.x;
    float d = 0.0f;
    if (i < NCH * NB) {
        double cnt = g_cnt[i];
        if (cnt > 0.0) {
            d = (float)fabs(g_sum_d[i] / cnt);
        }
        // reset for the next kernel_launch call (keeps launches deterministic)
        g_sum_d[i] = 0.0;
        g_cnt [i] = 0.0;
    }
    buf[i] = d;
    __syncthreads();
    #pragma unroll
    for (int s = 64; s > 0; s >>= 1) {
        if (i < s) buf[i] += buf[i + s];
        __syncthreads();
    }
    if (i == 0) out[0] = buf[0] / 96.0f;
}

extern "C" void kernel_launch(void* const* d_in, const int* in_sizes, int n_in,
                              void* d_out, int out_size)
{
    const float4* pred = (const float4*)d_in[0];
    const float4* targ = (const float4*)d_in[1];
    const float4* x    = (const float4*)d_in[2];
    float* out = (float*)d_out;

    hist_kernel<<<NCHUNKS * B_PER_CHUNK, THREADS>>>(pred, targ, x);
    final_kernel<<<1, 128>>>(out);
}